// round 10
// baseline (speedup 1.0000x reference)
#include <cuda_runtime.h>
#include <cuda_bf16.h>

#define Bn 8
#define Hn 56
#define Wn 56
#define Cn 64
#define Nn (Hn*Wn)      // 3136
#define En 64
#define NT 49
#define NSPLIT 2

// Q fp32, pre-scaled by 8*log2(e) so P = 2^S (ex2.approx).
// K hi/lo: bf16 [b][n][c]   (ldmatrix rows = keys)
// V hi/lo: bf16 [b][c][n]   (ldmatrix rows = chans)
__device__ float         g_Q [Bn*Nn*Cn];
__device__ __nv_bfloat16 g_Kh[Bn*Nn*Cn];
__device__ __nv_bfloat16 g_Kl[Bn*Nn*Cn];
__device__ __nv_bfloat16 g_Vh[Bn*Cn*Nn];
__device__ __nv_bfloat16 g_Vl[Bn*Cn*Nn];
// split-K partials
__device__ float g_Op[NSPLIT*Bn*Nn*Cn];
__device__ float g_Lp[NSPLIT*Bn*Nn];

#define QSCALE 11.54156036376953125f   // 8 * log2(e)

// ---------------------------------------------------------------------------
// Kernel 1: depthwise 3x3 conv; row staged in smem, coalesced writers.
// ---------------------------------------------------------------------------
#define RS 65

__global__ __launch_bounds__(256) void qkv_conv_kernel(
    const float* __restrict__ x,
    const float* __restrict__ wq, const float* __restrict__ bq,
    const float* __restrict__ wk, const float* __restrict__ bk,
    const float* __restrict__ wv, const float* __restrict__ bv)
{
    extern __shared__ float csm[];
    float* swq = csm;
    float* swk = swq + 9*Cn;
    float* swv = swk + 9*Cn;
    float* qrow = swv + 9*Cn;
    float* krow = qrow + Wn*RS;
    float* vrow = krow + Wn*RS;

    const int b = blockIdx.x / Hn;
    const int h = blockIdx.x % Hn;
    for (int i = threadIdx.x; i < 9*Cn; i += 256) {
        swq[i] = wq[i]; swk[i] = wk[i]; swv[i] = wv[i];
    }
    __syncthreads();

    for (int idx = threadIdx.x; idx < Wn*Cn; idx += 256) {
        const int w = idx >> 6;
        const int c = idx & 63;
        float aq = bq[c], ak = bk[c], av = bv[c];
        #pragma unroll
        for (int dh = 0; dh < 3; dh++) {
            const int hh = h + dh - 1;
            if (hh < 0 || hh >= Hn) continue;
            #pragma unroll
            for (int dw = 0; dw < 3; dw++) {
                const int ww = w + dw - 1;
                if (ww < 0 || ww >= Wn) continue;
                const float xv = x[((b*Hn + hh)*Wn + ww)*Cn + c];
                const int wi = (dh*3 + dw)*Cn + c;
                aq = fmaf(swq[wi], xv, aq);
                ak = fmaf(swk[wi], xv, ak);
                av = fmaf(swv[wi], xv, av);
            }
        }
        qrow[w*RS + c] = aq * QSCALE;
        krow[w*RS + c] = ak;
        vrow[w*RS + c] = av;
    }
    __syncthreads();

    {   // Q writer: [b][n][c]
        float* dst = g_Q + ((size_t)b*Nn + h*Wn)*Cn;
        for (int idx = threadIdx.x; idx < Wn*Cn; idx += 256)
            dst[idx] = qrow[(idx >> 6)*RS + (idx & 63)];
    }
    {   // K writer: bf16 hi/lo [b][n][c]
        __nv_bfloat16* dh_ = g_Kh + ((size_t)b*Nn + h*Wn)*Cn;
        __nv_bfloat16* dl_ = g_Kl + ((size_t)b*Nn + h*Wn)*Cn;
        for (int i = threadIdx.x; i < Wn*Cn; i += 256) {
            const float k = krow[(i >> 6)*RS + (i & 63)];
            __nv_bfloat16 hb = __float2bfloat16(k);
            dh_[i] = hb;
            dl_[i] = __float2bfloat16(k - __bfloat162float(hb));
        }
    }
    {   // V writer: bf16 hi/lo [b][c][n]
        __nv_bfloat16* dh_ = g_Vh + (size_t)b*Cn*Nn + h*Wn;
        __nv_bfloat16* dl_ = g_Vl + (size_t)b*Cn*Nn + h*Wn;
        for (int i = threadIdx.x; i < Cn*Wn; i += 256) {
            const int c = i / Wn;
            const int w = i - c*Wn;
            const float v = vrow[w*RS + c];
            __nv_bfloat16 hb = __float2bfloat16(v);
            dh_[(size_t)c*Nn + w] = hb;
            dl_[(size_t)c*Nn + w] = __float2bfloat16(v - __bfloat162float(hb));
        }
    }
}

// ---------------------------------------------------------------------------
#define MMA(d, a, b0, b1) \
  asm volatile("mma.sync.aligned.m16n8k16.row.col.f32.bf16.bf16.f32 " \
    "{%0,%1,%2,%3}, {%4,%5,%6,%7}, {%8,%9}, {%0,%1,%2,%3};" \
    : "+f"(d[0]), "+f"(d[1]), "+f"(d[2]), "+f"(d[3]) \
    : "r"(a[0]), "r"(a[1]), "r"(a[2]), "r"(a[3]), "r"(b0), "r"(b1))

__device__ __forceinline__ float ex2(float x) {
    float r;
    asm("ex2.approx.f32 %0, %1;" : "=f"(r) : "f"(x));
    return r;
}

__device__ __forceinline__ void bsplit2(float vx, float vy, unsigned& h, unsigned& l) {
    __nv_bfloat162 H = __floats2bfloat162_rn(vx, vy);
    float2 hf = __bfloat1622float2(H);
    __nv_bfloat162 L = __floats2bfloat162_rn(vx - hf.x, vy - hf.y);
    h = *(unsigned*)&H;
    l = *(unsigned*)&L;
}

__device__ __forceinline__ void cpa16(unsigned* dst, const uint4* src) {
    unsigned s = (unsigned)__cvta_generic_to_shared(dst);
    asm volatile("cp.async.cg.shared.global [%0], [%1], 16;" :: "r"(s), "l"(src));
}

__device__ __forceinline__ void ldsm4(unsigned& r0, unsigned& r1, unsigned& r2,
                                      unsigned& r3, const unsigned* p) {
    unsigned a = (unsigned)__cvta_generic_to_shared(p);
    asm volatile("ldmatrix.sync.aligned.m8n8.x4.shared.b16 {%0,%1,%2,%3}, [%4];"
        : "=r"(r0), "=r"(r1), "=r"(r2), "=r"(r3) : "r"(a));
}

#define PAIR3(A0, A1, AH, AL, PH, PL) do { \
    unsigned h0, h1, h2, h3, u0, u1, u2, u3; \
    ldsm4(h0, h1, h2, h3, PH); \
    ldsm4(u0, u1, u2, u3, PL); \
    MMA(A0, AH, h0, h1);  MMA(A1, AH, h2, h3); \
    MMA(A0, AL, h0, h1);  MMA(A1, AL, h2, h3); \
    MMA(A0, AH, u0, u1);  MMA(A1, AH, u2, u3); \
} while (0)

// ---------------------------------------------------------------------------
// Kernel 2: split-K flash attention partials (no-max base-2 softmax).
// grid (49, 8, 2), 128 threads. TK=64 tiles; split 0: tiles 0..24, split 1: 25..48.
// 48 KB smem (K single + V double) -> 4 CTAs/SM. Writes unnormalized O + l.
// ---------------------------------------------------------------------------
__global__ __launch_bounds__(128, 4) void attn_partial_kernel()
{
    extern __shared__ unsigned smem[];
    // words: [Kh 0..2047 | Kl 2048..4095 | Vbuf0 4096..8191 | Vbuf1 8192..12287]

    const int b    = blockIdx.y;
    const int q0   = blockIdx.x * 64;
    const int sp   = blockIdx.z;
    const int tid  = threadIdx.x;
    const int wp   = tid >> 5;
    const int lane = tid & 31;
    const int gr   = lane >> 2;
    const int q    = lane & 3;

    const int sw    = lane & 7;
    const int rbase = (8*(lane >> 4) + sw) * 32;
    const int kb    = (lane >> 3) & 1;

    const int kt0 = sp*25;           // 25 tiles for sp=0, 24 for sp=1
    const int nt  = 25 - sp;

    // ---- Q fragments (hi/lo) ----
    const float* Qb = g_Q + ((size_t)(b*Nn + q0 + 16*wp))*Cn;
    unsigned aQh[4][4], aQl[4][4];
    #pragma unroll
    for (int ks = 0; ks < 4; ks++) {
        const float* r0 = Qb + gr*64;
        const float* r1 = Qb + (gr + 8)*64;
        float2 v;
        v = *(const float2*)(r0 + 16*ks + 2*q);     bsplit2(v.x, v.y, aQh[ks][0], aQl[ks][0]);
        v = *(const float2*)(r1 + 16*ks + 2*q);     bsplit2(v.x, v.y, aQh[ks][1], aQl[ks][1]);
        v = *(const float2*)(r0 + 16*ks + 8 + 2*q); bsplit2(v.x, v.y, aQh[ks][2], aQl[ks][2]);
        v = *(const float2*)(r1 + 16*ks + 8 + 2*q); bsplit2(v.x, v.y, aQh[ks][3], aQl[ks][3]);
    }

    float oA[8][4];
    #pragma unroll
    for (int j = 0; j < 8; j++)
        #pragma unroll
        for (int i = 0; i < 4; i++) oA[j][i] = 0.0f;
    float l0 = 0.0f, l1 = 0.0f;

    const uint4* Kh4 = (const uint4*)(g_Kh + (size_t)b*Nn*Cn);
    const uint4* Kl4 = (const uint4*)(g_Kl + (size_t)b*Nn*Cn);
    const uint4* Vh4 = (const uint4*)(g_Vh + (size_t)b*Cn*Nn);
    const uint4* Vl4 = (const uint4*)(g_Vl + (size_t)b*Cn*Nn);

    auto issueK = [&](int kt) {
        #pragma unroll
        for (int it = 0; it < 4; it++) {
            const int f   = tid + it*128;
            const int row = f >> 3;
            const int ch  = f & 7;
            const int dw  = row*32 + ((ch ^ (row & 7)) << 2);
            cpa16(&smem[dw],        Kh4 + kt*512 + row*8 + ch);
            cpa16(&smem[2048 + dw], Kl4 + kt*512 + row*8 + ch);
        }
        asm volatile("cp.async.commit_group;" ::: "memory");
    };
    auto issueV = [&](int kt, int vb) {
        unsigned* base = smem + 4096 + vb*4096;
        #pragma unroll
        for (int it = 0; it < 4; it++) {
            const int f   = tid + it*128;
            const int row = f >> 3;
            const int ch  = f & 7;
            const int dw  = row*32 + ((ch ^ (row & 7)) << 2);
            cpa16(&base[dw],        Vh4 + row*(Nn/8) + kt*8 + ch);
            cpa16(&base[2048 + dw], Vl4 + row*(Nn/8) + kt*8 + ch);
        }
        asm volatile("cp.async.commit_group;" ::: "memory");
    };

    issueK(kt0);
    issueV(kt0, 0);
    int vb = 0;

    for (int t = 0; t < nt; t++) {
        asm volatile("cp.async.wait_group 0;" ::: "memory");
        __syncthreads();

        // ---- S = Q K^T ----
        float sA[8][4];
        #pragma unroll
        for (int j = 0; j < 8; j++)
            #pragma unroll
            for (int i = 0; i < 4; i++) sA[j][i] = 0.0f;
        #pragma unroll
        for (int ks = 0; ks < 4; ks++) {
            const int co = (((2*ks + kb) ^ sw) << 2) + rbase;
            #pragma unroll
            for (int jp = 0; jp < 4; jp++) {
                const unsigned* p = smem + jp*512 + co;
                PAIR3(sA[2*jp], sA[2*jp + 1], aQh[ks], aQl[ks], p, p + 2048);
            }
        }

        __syncthreads();                 // done reading K
        if (t + 1 < nt) {
            issueK(kt0 + t + 1);
            issueV(kt0 + t + 1, vb ^ 1);
        }

        // ---- P = 2^S, running sums ----
        #pragma unroll
        for (int j = 0; j < 8; j++) {
            sA[j][0] = ex2(sA[j][0]);
            sA[j][1] = ex2(sA[j][1]);
            sA[j][2] = ex2(sA[j][2]);
            sA[j][3] = ex2(sA[j][3]);
            l0 += sA[j][0] + sA[j][1];
            l1 += sA[j][2] + sA[j][3];
        }

        // ---- O += P V ----
        const unsigned* sV = smem + 4096 + vb*4096;
        #pragma unroll
        for (int ks = 0; ks < 4; ks++) {
            unsigned aPh[4], aPl[4];
            bsplit2(sA[2*ks    ][0], sA[2*ks    ][1], aPh[0], aPl[0]);
            bsplit2(sA[2*ks    ][2], sA[2*ks    ][3], aPh[1], aPl[1]);
            bsplit2(sA[2*ks + 1][0], sA[2*ks + 1][1], aPh[2], aPl[2]);
            bsplit2(sA[2*ks + 1][2], sA[2*ks + 1][3], aPh[3], aPl[3]);
            const int co = (((2*ks + kb) ^ sw) << 2) + rbase;
            #pragma unroll
            for (int jp = 0; jp < 4; jp++) {
                const unsigned* p = sV + jp*512 + co;
                PAIR3(oA[2*jp], oA[2*jp + 1], aPh, aPl, p, p + 2048);
            }
        }

        vb ^= 1;
    }

    // ---- write partials: unnormalized O + quad-reduced l ----
    l0 += __shfl_xor_sync(0xffffffffu, l0, 1);
    l0 += __shfl_xor_sync(0xffffffffu, l0, 2);
    l1 += __shfl_xor_sync(0xffffffffu, l1, 1);
    l1 += __shfl_xor_sync(0xffffffffu, l1, 2);

    const size_t rowbase = ((size_t)sp*Bn + b)*Nn + q0 + 16*wp;
    if (q == 0) {
        g_Lp[rowbase + gr    ] = l0;
        g_Lp[rowbase + gr + 8] = l1;
    }
    float* Or0 = g_Op + (rowbase + gr)*Cn;
    float* Or1 = Or0 + 8*Cn;
    #pragma unroll
    for (int j = 0; j < 8; j++) {
        *(float2*)&Or0[8*j + 2*q] = make_float2(oA[j][0], oA[j][1]);
        *(float2*)&Or1[8*j + 2*q] = make_float2(oA[j][2], oA[j][3]);
    }
}

// ---------------------------------------------------------------------------
// Kernel 3: combine splits + projection. grid (49, 8), 128 threads.
// ctx = (O0+O1)/(l0+l1); out = ctx @ Wp + bp  (bf16x3 MMA, Wp in smem)
// ---------------------------------------------------------------------------
__global__ __launch_bounds__(128) void combine_kernel(
    const float* __restrict__ Wp, const float* __restrict__ bp,
    float* __restrict__ out)
{
    __shared__ unsigned sWh[2048], sWl[2048];

    const int b    = blockIdx.y;
    const int q0   = blockIdx.x * 64;
    const int tid  = threadIdx.x;
    const int wp   = tid >> 5;
    const int lane = tid & 31;
    const int gr   = lane >> 2;
    const int q    = lane & 3;

    for (int i = tid; i < 4096; i += 128) {
        const int c = i >> 6, e = i & 63;
        const int pr = c >> 1;
        const float wv = Wp[i];
        __nv_bfloat16 hb = __float2bfloat16(wv);
        __nv_bfloat16 lb = __float2bfloat16(wv - __bfloat162float(hb));
        const int col = e ^ ((pr & 3) << 3);
        ((__nv_bfloat16*)sWh)[(pr*64 + col)*2 + (c & 1)] = hb;
        ((__nv_bfloat16*)sWl)[(pr*64 + col)*2 + (c & 1)] = lb;
    }
    __syncthreads();

    const size_t r0 = (size_t)b*Nn + q0 + 16*wp + gr;
    const size_t r1 = r0 + 8;
    const float inv0 = 1.0f / (g_Lp[r0] + g_Lp[(size_t)Bn*Nn + r0]);
    const float inv1 = 1.0f / (g_Lp[r1] + g_Lp[(size_t)Bn*Nn + r1]);

    const float* O0r0 = g_Op + r0*Cn;
    const float* O0r1 = g_Op + r1*Cn;
    const float* O1r0 = O0r0 + (size_t)Bn*Nn*Cn;
    const float* O1r1 = O0r1 + (size_t)Bn*Nn*Cn;

    float c0[8][2], c1[8][2];
    #pragma unroll
    for (int j = 0; j < 8; j++) {
        float2 a = *(const float2*)&O0r0[8*j + 2*q];
        float2 d = *(const float2*)&O1r0[8*j + 2*q];
        c0[j][0] = (a.x + d.x)*inv0;  c0[j][1] = (a.y + d.y)*inv0;
        a = *(const float2*)&O0r1[8*j + 2*q];
        d = *(const float2*)&O1r1[8*j + 2*q];
        c1[j][0] = (a.x + d.x)*inv1;  c1[j][1] = (a.y + d.y)*inv1;
    }

    float pA[8][4];
    #pragma unroll
    for (int j = 0; j < 8; j++)
        #pragma unroll
        for (int i = 0; i < 4; i++) pA[j][i] = 0.0f;

    #pragma unroll
    for (int ks = 0; ks < 4; ks++) {
        unsigned aCh[4], aCl[4];
        bsplit2(c0[2*ks    ][0], c0[2*ks    ][1], aCh[0], aCl[0]);
        bsplit2(c1[2*ks    ][0], c1[2*ks    ][1], aCh[1], aCl[1]);
        bsplit2(c0[2*ks + 1][0], c0[2*ks + 1][1], aCh[2], aCl[2]);
        bsplit2(c1[2*ks + 1][0], c1[2*ks + 1][1], aCh[3], aCl[3]);
        const unsigned* wh0 = &sWh[(8*ks + q    )*64];
        const unsigned* wh1 = &sWh[(8*ks + 4 + q)*64];
        const unsigned* wl0 = &sWl[(8*ks + q    )*64];
        const unsigned* wl1 = &sWl[(8*ks + 4 + q)*64];
        #pragma unroll
        for (int jg = 0; jg < 2; jg++) {
            unsigned bh0[4], bh1[4], bl0[4], bl1[4];
            #pragma unroll
            for (int j4 = 0; j4 < 4; j4++) {
                const int col = (8*(jg*4 + j4) + gr) ^ (q << 3);
                bh0[j4] = wh0[col]; bh1[j4] = wh1[col];
                bl0[j4] = wl0[col]; bl1[j4] = wl1[col];
            }
            #pragma unroll
            for (int j4 = 0; j4 < 4; j4++) MMA(pA[jg*4 + j4], aCh, bh0[j4], bh1[j4]);
            #pragma unroll
            for (int j4 = 0; j4 < 4; j4++) MMA(pA[jg*4 + j4], aCl, bh0[j4], bh1[j4]);
            #pragma unroll
            for (int j4 = 0; j4 < 4; j4++) MMA(pA[jg*4 + j4], aCh, bl0[j4], bl1[j4]);
        }
    }

    float* orow0 = out + r0*En;
    float* orow1 = out + r1*En;
    #pragma unroll
    for (int j = 0; j < 8; j++) {
        const float2 bv = *(const float2*)&bp[8*j + 2*q];
        *(float2*)&orow0[8*j + 2*q] = make_float2(pA[j][0] + bv.x, pA[j][1] + bv.y);
        *(float2*)&orow1[8*j + 2*q] = make_float2(pA[j][2] + bv.x, pA[j][3] + bv.y);
    }
}

// ---------------------------------------------------------------------------
extern "C" void kernel_launch(void* const* d_in, const int* in_sizes, int n_in,
                              void* d_out, int out_size)
{
    const float* x  = (const float*)d_in[0];
    const float* wq = (const float*)d_in[1];
    const float* bq = (const float*)d_in[2];
    const float* wk = (const float*)d_in[3];
    const float* bk = (const float*)d_in[4];
    const float* wv = (const float*)d_in[5];
    const float* bv = (const float*)d_in[6];
    const float* Wp = (const float*)d_in[7];
    const float* bp = (const float*)d_in[8];
    float* out = (float*)d_out;

    const int conv_smem = (27*Cn + 3*Wn*RS) * 4;   // 50592
    cudaFuncSetAttribute(qkv_conv_kernel,
                         cudaFuncAttributeMaxDynamicSharedMemorySize, conv_smem);
    const int smem_bytes = 12288*4;   // 48 KB
    cudaFuncSetAttribute(attn_partial_kernel,
                         cudaFuncAttributeMaxDynamicSharedMemorySize, smem_bytes);

    qkv_conv_kernel<<<Bn*Hn, 256, conv_smem>>>(x, wq, bq, wk, bk, wv, bv);

    dim3 grid(Nn/64, Bn, NSPLIT);
    attn_partial_kernel<<<grid, 128, smem_bytes>>>();

    dim3 cgrid(Nn/64, Bn);
    combine_kernel<<<cgrid, 128>>>(Wp, bp, out);
}

// round 11
// speedup vs baseline: 1.0851x; 1.0851x over previous
#include <cuda_runtime.h>
#include <cuda_bf16.h>

#define Bn 8
#define Hn 56
#define Wn 56
#define Cn 64
#define Nn (Hn*Wn)      // 3136
#define En 64
#define NT 49           // 3136/64 k-tiles

// Q fp32, pre-scaled by 8*log2(e) so P = 2^S (ex2.approx).
// K hi/lo: bf16 [b][n][c]   (ldmatrix rows = keys)
// V hi/lo: bf16 [b][c][n]   (ldmatrix rows = chans)
__device__ float         g_Q [Bn*Nn*Cn];
__device__ __nv_bfloat16 g_Kh[Bn*Nn*Cn];
__device__ __nv_bfloat16 g_Kl[Bn*Nn*Cn];
__device__ __nv_bfloat16 g_Vh[Bn*Cn*Nn];
__device__ __nv_bfloat16 g_Vl[Bn*Cn*Nn];

#define QSCALE 11.54156036376953125f   // 8 * log2(e)

// ---------------------------------------------------------------------------
// Kernel 1: depthwise 3x3 conv; float4 compute, row staged in smem,
// coalesced writers.
// ---------------------------------------------------------------------------
#define RS 65

__global__ __launch_bounds__(256) void qkv_conv_kernel(
    const float* __restrict__ x,
    const float* __restrict__ wq, const float* __restrict__ bq,
    const float* __restrict__ wk, const float* __restrict__ bk,
    const float* __restrict__ wv, const float* __restrict__ bv)
{
    extern __shared__ float csm[];
    float* swq = csm;
    float* swk = swq + 9*Cn;
    float* swv = swk + 9*Cn;
    float* qrow = swv + 9*Cn;
    float* krow = qrow + Wn*RS;
    float* vrow = krow + Wn*RS;

    const int b = blockIdx.x / Hn;
    const int h = blockIdx.x % Hn;
    for (int i = threadIdx.x; i < 9*Cn; i += 256) {
        swq[i] = wq[i]; swk[i] = wk[i]; swv[i] = wv[i];
    }
    __syncthreads();

    // ---- compute conv row, 4 channels per thread-iter ----
    for (int idx = threadIdx.x; idx < Wn*(Cn/4); idx += 256) {
        const int w  = idx >> 4;            // Cn/4 = 16
        const int c4 = (idx & 15) << 2;
        float4 aq = *(const float4*)&bq[c4];
        float4 ak = *(const float4*)&bk[c4];
        float4 av = *(const float4*)&bv[c4];
        #pragma unroll
        for (int dh = 0; dh < 3; dh++) {
            const int hh = h + dh - 1;
            if (hh < 0 || hh >= Hn) continue;
            #pragma unroll
            for (int dw = 0; dw < 3; dw++) {
                const int ww = w + dw - 1;
                if (ww < 0 || ww >= Wn) continue;
                const float4 xv = *(const float4*)&x[((b*Hn + hh)*Wn + ww)*Cn + c4];
                const int wi = (dh*3 + dw)*Cn + c4;
                const float4 q4 = *(const float4*)&swq[wi];
                const float4 k4 = *(const float4*)&swk[wi];
                const float4 v4 = *(const float4*)&swv[wi];
                aq.x = fmaf(q4.x, xv.x, aq.x); aq.y = fmaf(q4.y, xv.y, aq.y);
                aq.z = fmaf(q4.z, xv.z, aq.z); aq.w = fmaf(q4.w, xv.w, aq.w);
                ak.x = fmaf(k4.x, xv.x, ak.x); ak.y = fmaf(k4.y, xv.y, ak.y);
                ak.z = fmaf(k4.z, xv.z, ak.z); ak.w = fmaf(k4.w, xv.w, ak.w);
                av.x = fmaf(v4.x, xv.x, av.x); av.y = fmaf(v4.y, xv.y, av.y);
                av.z = fmaf(v4.z, xv.z, av.z); av.w = fmaf(v4.w, xv.w, av.w);
            }
        }
        float* qd = &qrow[w*RS + c4];
        qd[0] = aq.x*QSCALE; qd[1] = aq.y*QSCALE; qd[2] = aq.z*QSCALE; qd[3] = aq.w*QSCALE;
        float* kd = &krow[w*RS + c4];
        kd[0] = ak.x; kd[1] = ak.y; kd[2] = ak.z; kd[3] = ak.w;
        float* vd = &vrow[w*RS + c4];
        vd[0] = av.x; vd[1] = av.y; vd[2] = av.z; vd[3] = av.w;
    }
    __syncthreads();

    {   // Q writer: [b][n][c]
        float* dst = g_Q + ((size_t)b*Nn + h*Wn)*Cn;
        for (int idx = threadIdx.x; idx < Wn*Cn; idx += 256)
            dst[idx] = qrow[(idx >> 6)*RS + (idx & 63)];
    }
    {   // K writer: bf16 hi/lo [b][n][c]
        __nv_bfloat16* dh_ = g_Kh + ((size_t)b*Nn + h*Wn)*Cn;
        __nv_bfloat16* dl_ = g_Kl + ((size_t)b*Nn + h*Wn)*Cn;
        for (int i = threadIdx.x; i < Wn*Cn; i += 256) {
            const float k = krow[(i >> 6)*RS + (i & 63)];
            __nv_bfloat16 hb = __float2bfloat16(k);
            dh_[i] = hb;
            dl_[i] = __float2bfloat16(k - __bfloat162float(hb));
        }
    }
    {   // V writer: bf16 hi/lo [b][c][n]
        __nv_bfloat16* dh_ = g_Vh + (size_t)b*Cn*Nn + h*Wn;
        __nv_bfloat16* dl_ = g_Vl + (size_t)b*Cn*Nn + h*Wn;
        for (int i = threadIdx.x; i < Cn*Wn; i += 256) {
            const int c = i / Wn;
            const int w = i - c*Wn;
            const float v = vrow[w*RS + c];
            __nv_bfloat16 hb = __float2bfloat16(v);
            dh_[(size_t)c*Nn + w] = hb;
            dl_[(size_t)c*Nn + w] = __float2bfloat16(v - __bfloat162float(hb));
        }
    }
}

// ---------------------------------------------------------------------------
// Kernel 2: flash attention (no-max base-2 softmax) + projection.
// Fused jp-loop: S column-block -> exp -> matching PV k-step, so scalar
// work is 4x smaller per chunk and hides under tensor-pipe drain.
// ---------------------------------------------------------------------------
#define MMA(d, a, b0, b1) \
  asm volatile("mma.sync.aligned.m16n8k16.row.col.f32.bf16.bf16.f32 " \
    "{%0,%1,%2,%3}, {%4,%5,%6,%7}, {%8,%9}, {%0,%1,%2,%3};" \
    : "+f"(d[0]), "+f"(d[1]), "+f"(d[2]), "+f"(d[3]) \
    : "r"(a[0]), "r"(a[1]), "r"(a[2]), "r"(a[3]), "r"(b0), "r"(b1))

__device__ __forceinline__ float ex2(float x) {
    float r;
    asm("ex2.approx.f32 %0, %1;" : "=f"(r) : "f"(x));
    return r;
}

__device__ __forceinline__ void bsplit2(float vx, float vy, unsigned& h, unsigned& l) {
    __nv_bfloat162 H = __floats2bfloat162_rn(vx, vy);
    float2 hf = __bfloat1622float2(H);
    __nv_bfloat162 L = __floats2bfloat162_rn(vx - hf.x, vy - hf.y);
    h = *(unsigned*)&H;
    l = *(unsigned*)&L;
}

__device__ __forceinline__ void cpa16(unsigned* dst, const uint4* src) {
    unsigned s = (unsigned)__cvta_generic_to_shared(dst);
    asm volatile("cp.async.cg.shared.global [%0], [%1], 16;" :: "r"(s), "l"(src));
}

__device__ __forceinline__ void ldsm4(unsigned& r0, unsigned& r1, unsigned& r2,
                                      unsigned& r3, const unsigned* p) {
    unsigned a = (unsigned)__cvta_generic_to_shared(p);
    asm volatile("ldmatrix.sync.aligned.m8n8.x4.shared.b16 {%0,%1,%2,%3}, [%4];"
        : "=r"(r0), "=r"(r1), "=r"(r2), "=r"(r3) : "r"(a));
}

#define PAIR3(A0, A1, AH, AL, PH, PL) do { \
    unsigned h0, h1, h2, h3, u0, u1, u2, u3; \
    ldsm4(h0, h1, h2, h3, PH); \
    ldsm4(u0, u1, u2, u3, PL); \
    MMA(A0, AH, h0, h1);  MMA(A1, AH, h2, h3); \
    MMA(A0, AL, h0, h1);  MMA(A1, AL, h2, h3); \
    MMA(A0, AH, u0, u1);  MMA(A1, AH, u2, u3); \
} while (0)

__global__ __launch_bounds__(128, 3) void attn_kernel(
    const float* __restrict__ Wp, const float* __restrict__ bp,
    float* __restrict__ out)
{
    extern __shared__ unsigned smem[];   // 2 x 8192 words: [Kh|Kl|Vh|Vl] x 2048

    const int b    = blockIdx.y;
    const int q0   = blockIdx.x * 64;
    const int tid  = threadIdx.x;
    const int wp   = tid >> 5;
    const int lane = tid & 31;
    const int gr   = lane >> 2;
    const int q    = lane & 3;

    const int sw    = lane & 7;
    const int rbase = (8*(lane >> 4) + sw) * 32;
    const int kb    = (lane >> 3) & 1;

    // ---- Q fragments (hi/lo), rows 16wp+{gr,gr+8} ----
    const float* Qb = g_Q + ((size_t)(b*Nn + q0 + 16*wp))*Cn;
    unsigned aQh[4][4], aQl[4][4];
    #pragma unroll
    for (int ks = 0; ks < 4; ks++) {
        const float* r0 = Qb + gr*64;
        const float* r1 = Qb + (gr + 8)*64;
        float2 v;
        v = *(const float2*)(r0 + 16*ks + 2*q);     bsplit2(v.x, v.y, aQh[ks][0], aQl[ks][0]);
        v = *(const float2*)(r1 + 16*ks + 2*q);     bsplit2(v.x, v.y, aQh[ks][1], aQl[ks][1]);
        v = *(const float2*)(r0 + 16*ks + 8 + 2*q); bsplit2(v.x, v.y, aQh[ks][2], aQl[ks][2]);
        v = *(const float2*)(r1 + 16*ks + 8 + 2*q); bsplit2(v.x, v.y, aQh[ks][3], aQl[ks][3]);
    }

    float oA[8][4];
    #pragma unroll
    for (int j = 0; j < 8; j++)
        #pragma unroll
        for (int i = 0; i < 4; i++) oA[j][i] = 0.0f;
    float l0 = 0.0f, l1 = 0.0f;

    const uint4* Kh4 = (const uint4*)(g_Kh + (size_t)b*Nn*Cn);
    const uint4* Kl4 = (const uint4*)(g_Kl + (size_t)b*Nn*Cn);
    const uint4* Vh4 = (const uint4*)(g_Vh + (size_t)b*Cn*Nn);
    const uint4* Vl4 = (const uint4*)(g_Vl + (size_t)b*Cn*Nn);

    auto issue_tile = [&](int kt, int bufsel) {
        unsigned* base = smem + bufsel*8192;
        #pragma unroll
        for (int it = 0; it < 4; it++) {
            const int f   = tid + it*128;
            const int row = f >> 3;
            const int ch  = f & 7;
            const int dw  = row*32 + ((ch ^ (row & 7)) << 2);
            cpa16(&base[dw],        Kh4 + kt*512 + row*8 + ch);
            cpa16(&base[2048 + dw], Kl4 + kt*512 + row*8 + ch);
            cpa16(&base[4096 + dw], Vh4 + row*(Nn/8) + kt*8 + ch);
            cpa16(&base[6144 + dw], Vl4 + row*(Nn/8) + kt*8 + ch);
        }
        asm volatile("cp.async.commit_group;" ::: "memory");
    };

    issue_tile(0, 0);
    int buf = 0;

    for (int kt = 0; kt < NT; kt++) {
        asm volatile("cp.async.wait_group 0;" ::: "memory");
        __syncthreads();
        if (kt + 1 < NT) issue_tile(kt + 1, buf ^ 1);

        const unsigned* sKh = smem + buf*8192;
        const unsigned* sVh = sKh + 4096;

        // ---- fused: per 16-key column block: S -> exp -> PV k-step ----
        #pragma unroll
        for (int jp = 0; jp < 4; jp++) {
            float sA0[4] = {0.f, 0.f, 0.f, 0.f};
            float sA1[4] = {0.f, 0.f, 0.f, 0.f};
            #pragma unroll
            for (int ks = 0; ks < 4; ks++) {
                const int co = (((2*ks + kb) ^ sw) << 2) + rbase;
                const unsigned* p = sKh + jp*512 + co;
                PAIR3(sA0, sA1, aQh[ks], aQl[ks], p, p + 2048);
            }

            // exp (base-2) + running row sums — same element order as before
            sA0[0] = ex2(sA0[0]); sA0[1] = ex2(sA0[1]);
            sA0[2] = ex2(sA0[2]); sA0[3] = ex2(sA0[3]);
            l0 += sA0[0] + sA0[1];
            l1 += sA0[2] + sA0[3];
            sA1[0] = ex2(sA1[0]); sA1[1] = ex2(sA1[1]);
            sA1[2] = ex2(sA1[2]); sA1[3] = ex2(sA1[3]);
            l0 += sA1[0] + sA1[1];
            l1 += sA1[2] + sA1[3];

            // P fragments for this k-step (keys 16jp..16jp+15)
            unsigned aPh[4], aPl[4];
            bsplit2(sA0[0], sA0[1], aPh[0], aPl[0]);
            bsplit2(sA0[2], sA0[3], aPh[1], aPl[1]);
            bsplit2(sA1[0], sA1[1], aPh[2], aPl[2]);
            bsplit2(sA1[2], sA1[3], aPh[3], aPl[3]);

            // PV k-step jp over all 4 output-channel blocks
            const int cov = (((2*jp + kb) ^ sw) << 2) + rbase;
            #pragma unroll
            for (int jv = 0; jv < 4; jv++) {
                const unsigned* p = sVh + jv*512 + cov;
                PAIR3(oA[2*jv], oA[2*jv + 1], aPh, aPl, p, p + 2048);
            }
        }

        buf ^= 1;
    }

    // ============= epilogue: ctx = O/l; out = ctx @ Wp + bp =============
    l0 += __shfl_xor_sync(0xffffffffu, l0, 1);
    l0 += __shfl_xor_sync(0xffffffffu, l0, 2);
    l1 += __shfl_xor_sync(0xffffffffu, l1, 1);
    l1 += __shfl_xor_sync(0xffffffffu, l1, 2);
    const float inv0 = 1.0f / l0;
    const float inv1 = 1.0f / l1;

    __syncthreads();
    __nv_bfloat16* sWh = (__nv_bfloat16*)smem;
    __nv_bfloat16* sWl = (__nv_bfloat16*)(smem + 2048);
    for (int i = tid; i < 4096; i += 128) {
        const int c = i >> 6, e = i & 63;
        const float wv = Wp[i];
        __nv_bfloat16 hb = __float2bfloat16(wv);
        const int o = e*64 + ((((c >> 3) ^ (e & 7))) << 3) + (c & 7);
        sWh[o] = hb;
        sWl[o] = __float2bfloat16(wv - __bfloat162float(hb));
    }
    __syncthreads();

    float pA[8][4];
    #pragma unroll
    for (int j = 0; j < 8; j++)
        #pragma unroll
        for (int i = 0; i < 4; i++) pA[j][i] = 0.0f;
    #pragma unroll
    for (int ks = 0; ks < 4; ks++) {
        unsigned aCh[4], aCl[4];
        bsplit2(oA[2*ks    ][0]*inv0, oA[2*ks    ][1]*inv0, aCh[0], aCl[0]);
        bsplit2(oA[2*ks    ][2]*inv1, oA[2*ks    ][3]*inv1, aCh[1], aCl[1]);
        bsplit2(oA[2*ks + 1][0]*inv0, oA[2*ks + 1][1]*inv0, aCh[2], aCl[2]);
        bsplit2(oA[2*ks + 1][2]*inv1, oA[2*ks + 1][3]*inv1, aCh[3], aCl[3]);
        const int co = (((2*ks + kb) ^ sw) << 2) + rbase;
        #pragma unroll
        for (int jp = 0; jp < 4; jp++) {
            const unsigned* p = smem + jp*512 + co;
            PAIR3(pA[2*jp], pA[2*jp + 1], aCh, aCl, p, p + 2048);
        }
    }

    float* orow0 = out + (size_t)(b*Nn + q0 + 16*wp + gr)*En;
    float* orow1 = orow0 + 8*En;
    #pragma unroll
    for (int j = 0; j < 8; j++) {
        const float2 bv = *(const float2*)&bp[8*j + 2*q];
        *(float2*)&orow0[8*j + 2*q] = make_float2(pA[j][0] + bv.x, pA[j][1] + bv.y);
        *(float2*)&orow1[8*j + 2*q] = make_float2(pA[j][2] + bv.x, pA[j][3] + bv.y);
    }
}

// ---------------------------------------------------------------------------
extern "C" void kernel_launch(void* const* d_in, const int* in_sizes, int n_in,
                              void* d_out, int out_size)
{
    const float* x  = (const float*)d_in[0];
    const float* wq = (const float*)d_in[1];
    const float* bq = (const float*)d_in[2];
    const float* wk = (const float*)d_in[3];
    const float* bk = (const float*)d_in[4];
    const float* wv = (const float*)d_in[5];
    const float* bv = (const float*)d_in[6];
    const float* Wp = (const float*)d_in[7];
    const float* bp = (const float*)d_in[8];
    float* out = (float*)d_out;

    const int conv_smem = (27*Cn + 3*Wn*RS) * 4;   // 50592
    cudaFuncSetAttribute(qkv_conv_kernel,
                         cudaFuncAttributeMaxDynamicSharedMemorySize, conv_smem);
    const int smem_bytes = 2*8192*4;   // 65536
    cudaFuncSetAttribute(attn_kernel,
                         cudaFuncAttributeMaxDynamicSharedMemorySize, smem_bytes);

    qkv_conv_kernel<<<Bn*Hn, 256, conv_smem>>>(x, wq, bq, wk, bk, wv, bv);

    dim3 grid(NT, Bn);
    attn_kernel<<<grid, 128, smem_bytes>>>(Wp, bp, out);
}